// round 15
// baseline (speedup 1.0000x reference)
#include <cuda_runtime.h>
#include <cuda_fp16.h>
#include <math.h>

// Problem constants
#define B_       2
#define T_       2048
#define C_       2048
#define NH_      16
#define HD_      128
#define GATE_CH_ 32
#define M_       (B_*T_)   // 4096 rows

// ---------------------------------------------------------------------------
// Scratch (device globals: allocation-free per harness rules)
// ---------------------------------------------------------------------------
__device__ __half g_xf[(size_t)M_*C_];
__device__ __half g_yf[(size_t)M_*C_];
__device__ __half g_qf[(size_t)M_*C_];
__device__ __half g_kf[(size_t)M_*C_];
__device__ __half g_vf[(size_t)M_*C_];
__device__ __half g_wt[4][(size_t)C_*C_];   // transposed [N][K] Wq,Wk,Wv,Wproj

// ---------------------------------------------------------------------------
// PTX helpers
// ---------------------------------------------------------------------------
__device__ __forceinline__ unsigned smem_u32(const void* p) {
    unsigned a;
    asm("{ .reg .u64 t; cvta.to.shared.u64 t, %1; cvt.u32.u64 %0, t; }"
        : "=r"(a) : "l"(p));
    return a;
}

#define CP_ASYNC16(dst_u32, src_ptr) \
    asm volatile("cp.async.cg.shared.global [%0], [%1], 16;" \
                 :: "r"(dst_u32), "l"(src_ptr))
#define CP_COMMIT() asm volatile("cp.async.commit_group;" ::: "memory")
#define CP_WAIT0()  asm volatile("cp.async.wait_group 0;" ::: "memory")
#define CP_WAIT1()  asm volatile("cp.async.wait_group 1;" ::: "memory")

__device__ __forceinline__ void ldmatrix_x4(unsigned* r, unsigned addr) {
    asm volatile("ldmatrix.sync.aligned.m8n8.x4.shared.b16 {%0,%1,%2,%3}, [%4];"
                 : "=r"(r[0]), "=r"(r[1]), "=r"(r[2]), "=r"(r[3]) : "r"(addr));
}
__device__ __forceinline__ void ldmatrix_x4_trans(unsigned* r, unsigned addr) {
    asm volatile("ldmatrix.sync.aligned.m8n8.x4.trans.shared.b16 {%0,%1,%2,%3}, [%4];"
                 : "=r"(r[0]), "=r"(r[1]), "=r"(r[2]), "=r"(r[3]) : "r"(addr));
}
__device__ __forceinline__ void mma_f16(float* c, const unsigned* a, const unsigned* b) {
    asm volatile(
        "mma.sync.aligned.m16n8k16.row.col.f32.f16.f16.f32 "
        "{%0,%1,%2,%3}, {%4,%5,%6,%7}, {%8,%9}, {%0,%1,%2,%3};"
        : "+f"(c[0]), "+f"(c[1]), "+f"(c[2]), "+f"(c[3])
        : "r"(a[0]), "r"(a[1]), "r"(a[2]), "r"(a[3]), "r"(b[0]), "r"(b[1]));
}
__device__ __forceinline__ unsigned pack_h2(float lo, float hi) {
    __half2 h = __float22half2_rn(make_float2(lo, hi));
    return *reinterpret_cast<unsigned*>(&h);
}
// two fp16 exp2's in one MUFU op
__device__ __forceinline__ unsigned ex2_h2(unsigned x) {
    unsigned y;
    asm("ex2.approx.f16x2 %0, %1;" : "=r"(y) : "r"(x));
    return y;
}
__device__ __forceinline__ float warp_sum(float v) {
    #pragma unroll
    for (int d = 16; d >= 1; d >>= 1) v += __shfl_xor_sync(0xffffffffu, v, d);
    return v;
}

// scale * log2(e), folded into q at QKV epilogue
#define QSC (0.08838834764831845f * 1.4426950408889634f)
// fixed softmax reference (log2 units). |t| <= 16.33 by Cauchy-Schwarz on
// RMS-normed q,k, so p = 2^(t-5) in [2^-21.3, 2^11.3]: provably no fp16
// overflow and no subnormal flush-to-zero of any term.
#define FMAX_REF 5.0f

// ---------------------------------------------------------------------------
// prep_inputs: z<4: transpose W[K][N] fp32 -> g_wt[z][N][K] fp16;
//              z=4: convert x fp32 -> g_xf fp16.
// ---------------------------------------------------------------------------
__global__ __launch_bounds__(256) void prep_inputs(
    const float* __restrict__ x,
    const float* __restrict__ Wq, const float* __restrict__ Wk,
    const float* __restrict__ Wv, const float* __restrict__ Wproj)
{
    __shared__ float tile[32][33];
    const int z = blockIdx.z;
    const int tid = threadIdx.y * 32 + threadIdx.x;

    if (z == 4) {
        const int idx0 = (blockIdx.y * 64 + blockIdx.x) * 256 + tid;
        #pragma unroll
        for (int r = 0; r < 2; r++) {
            const int i = idx0 + r * (64 * 64 * 256);
            float4 v = ((const float4*)x)[i];
            __half2* op = (__half2*)(g_xf + (size_t)i * 4);
            op[0] = __float22half2_rn(make_float2(v.x, v.y));
            op[1] = __float22half2_rn(make_float2(v.z, v.w));
        }
        return;
    }

    const float* W = (z == 0) ? Wq : (z == 1) ? Wk : (z == 2) ? Wv : Wproj;
    __half* out = g_wt[z];
    int k0 = blockIdx.y * 32, n0 = blockIdx.x * 32;
    int tx = threadIdx.x, ty = threadIdx.y;
    #pragma unroll
    for (int r = 0; r < 4; r++)
        tile[ty + 8 * r][tx] = W[(size_t)(k0 + ty + 8 * r) * C_ + n0 + tx];
    __syncthreads();
    #pragma unroll
    for (int r = 0; r < 4; r++) {
        float v = tile[tx][ty + 8 * r];
        out[(size_t)(n0 + ty + 8 * r) * C_ + k0 + tx] = __float2half(v);
    }
}

// ---------------------------------------------------------------------------
// HMMA fp16 GEMM mainloop (round-12 form, unchanged).
// ---------------------------------------------------------------------------
#define KC        64
#define AS_STRIDE 72
#define TILE_E    (128 * AS_STRIDE)
#define STAGE_E   (2 * TILE_E)
#define NSTAGE    3

__device__ __forceinline__ void gemm_mainloop(
    const __half* __restrict__ A, const __half* __restrict__ Bm,
    int m0, int n0, int K, __half* smb, float acc[2][8][4])
{
    const int tid = threadIdx.x, wid = tid >> 5, lane = tid & 31;
    const int NCH = K / KC;
    const int wm = wid & 3;
    const int wn = wid >> 2;

    auto load_slice = [&](int c, int s, int i) {
        const int k0 = c * KC;
        __half* base = smb + s * STAGE_E;
        int cidx = tid + i * 256;
        int row  = cidx >> 3;
        int col8 = (cidx & 7) * 8;
        unsigned so = smem_u32(base + row * AS_STRIDE + col8);
        CP_ASYNC16(so,              A  + (size_t)(m0 + row) * K + k0 + col8);
        CP_ASYNC16(so + TILE_E * 2, Bm + (size_t)(n0 + row) * K + k0 + col8);
    };

    #pragma unroll
    for (int mt = 0; mt < 2; mt++)
        #pragma unroll
        for (int nt = 0; nt < 8; nt++)
            #pragma unroll
            for (int r = 0; r < 4; r++) acc[mt][nt][r] = 0.f;

    #pragma unroll
    for (int i = 0; i < 4; i++) load_slice(0, 0, i);
    CP_COMMIT();
    #pragma unroll
    for (int i = 0; i < 4; i++) load_slice(1, 1, i);
    CP_COMMIT();

    const int a_row = wm * 32 + (lane & 15);
    const int a_k8  = (lane >> 4) * 8;
    const int b_r   = lane & 7;
    const int b_grp = lane >> 3;
    const int b_row = wn * 64 + (b_grp >> 1) * 8 + b_r;
    const int b_k8  = (b_grp & 1) * 8;

    for (int c = 0; c < NCH; c++) {
        if (c + 1 < NCH) CP_WAIT1();
        else             CP_WAIT0();
        __syncthreads();

        const __half* st = smb + (c % NSTAGE) * STAGE_E;
        const __half* sA = st;
        const __half* sB = st + TILE_E;
        const bool pf = (c + 2 < NCH);
        const int  ps = (c + 2) % NSTAGE;

        #pragma unroll
        for (int k16 = 0; k16 < 4; k16++) {
            if (pf) load_slice(c + 2, ps, k16);
            const int kb = k16 * 16;
            unsigned ah[2][4];
            #pragma unroll
            for (int mt = 0; mt < 2; mt++)
                ldmatrix_x4(ah[mt], smem_u32(sA + (a_row + mt * 16) * AS_STRIDE + kb + a_k8));
            unsigned bh[4][4];
            #pragma unroll
            for (int j = 0; j < 4; j++)
                ldmatrix_x4(bh[j], smem_u32(sB + (b_row + j * 16) * AS_STRIDE + kb + b_k8));
            #pragma unroll
            for (int j = 0; j < 4; j++)
                #pragma unroll
                for (int t = 0; t < 2; t++)
                    #pragma unroll
                    for (int mt = 0; mt < 2; mt++)
                        mma_f16(acc[mt][j * 2 + t], ah[mt], bh[j] + t * 2);
        }
        if (pf) CP_COMMIT();
    }
    __syncthreads();
}

// ---------------------------------------------------------------------------
// Fused QKV GEMM + prep epilogue.
// ---------------------------------------------------------------------------
#define EST 130

__global__ __launch_bounds__(256, 2) void gemm_qkv_fused(
    const __half* __restrict__ A,
    const float* __restrict__ x, const float* __restrict__ ve,
    const float* __restrict__ cosb, const float* __restrict__ sinb,
    const float* __restrict__ Wgate)
{
    extern __shared__ __half smb[];
    const int z = blockIdx.z;
    const int m0 = blockIdx.y * 128, n0 = blockIdx.x * 128;

    float acc[2][8][4];
    gemm_mainloop(A, g_wt[z], m0, n0, C_, smb, acc);

    const int tid = threadIdx.x, wid = tid >> 5, lane = tid & 31;
    const int wm = wid & 3, wn = wid >> 2;
    const int cg = lane >> 2, ct = lane & 3;
    float* ft = (float*)smb;
    #pragma unroll
    for (int mt = 0; mt < 2; mt++) {
        const int r = wm * 32 + mt * 16 + cg;
        #pragma unroll
        for (int nt = 0; nt < 8; nt++) {
            const int cc = wn * 64 + nt * 8 + ct * 2;
            ft[r * EST + cc]           = acc[mt][nt][0];
            ft[r * EST + cc + 1]       = acc[mt][nt][1];
            ft[(r + 8) * EST + cc]     = acc[mt][nt][2];
            ft[(r + 8) * EST + cc + 1] = acc[mt][nt][3];
        }
    }
    __syncthreads();

    const int h = n0 >> 7;
    if (z < 2) {
        __half* gout = (z == 0) ? g_qf : g_kf;
        const float post = (z == 0) ? QSC : 1.f;
        for (int rr = 0; rr < 16; rr++) {
            const int r = wid * 16 + rr;
            const int row = m0 + r;
            const int t = row & (T_ - 1);
            const float* fr = ft + r * EST;
            const float* cr = cosb + (size_t)t * 64;
            const float* sr = sinb + (size_t)t * 64;
            const int d0 = lane, d1 = lane + 32;
            float x1a = fr[d0], x2a = fr[d0 + 64];
            float x1b = fr[d1], x2b = fr[d1 + 64];
            float ca = cr[d0], sa = sr[d0], cb = cr[d1], sb = sr[d1];
            float o1a =  x1a * ca + x2a * sa;
            float o2a = -x1a * sa + x2a * ca;
            float o1b =  x1b * cb + x2b * sb;
            float o2b = -x1b * sb + x2b * cb;
            float ss = warp_sum(o1a*o1a + o2a*o2a + o1b*o1b + o2b*o2b);
            float rn = rsqrtf(ss * (1.f / 128.f) + 1e-6f) * post;
            __half* dst = gout + (size_t)row * C_ + n0;
            dst[d0]      = __float2half(o1a * rn);
            dst[d0 + 64] = __float2half(o2a * rn);
            dst[d1]      = __float2half(o1b * rn);
            dst[d1 + 64] = __float2half(o2b * rn);
        }
    } else {
        for (int rr = 0; rr < 16; rr++) {
            const int r = wid * 16 + rr;
            const int row = m0 + r;
            const float* fr = ft + r * EST;
            float sg = warp_sum(x[(size_t)row * C_ + lane] * Wgate[lane * NH_ + h]);
            float gt = 2.f / (1.f + __expf(-sg));
            __half* dst = g_vf + (size_t)row * C_ + n0;
            const float* vep = ve + (size_t)row * C_ + n0;
            #pragma unroll
            for (int i2 = 0; i2 < 4; i2++) {
                const int d = lane + i2 * 32;
                dst[d] = __float2half(fr[d] + gt * vep[d]);
            }
        }
    }
}

__global__ __launch_bounds__(256, 2) void gemm_proj(
    const __half* __restrict__ A, float* __restrict__ Cm)
{
    extern __shared__ __half smb[];
    const int m0 = blockIdx.y * 128, n0 = blockIdx.x * 128;
    float acc[2][8][4];
    gemm_mainloop(A, g_wt[3], m0, n0, C_, smb, acc);

    const int tid = threadIdx.x, wid = tid >> 5, lane = tid & 31;
    const int wm = wid & 3, wn = wid >> 2;
    const int cg = lane >> 2, ct = lane & 3;
    #pragma unroll
    for (int mt = 0; mt < 2; mt++) {
        const int row = m0 + wm * 32 + mt * 16 + cg;
        #pragma unroll
        for (int nt = 0; nt < 8; nt++) {
            const int col = n0 + wn * 64 + nt * 8 + ct * 2;
            *(float2*)(Cm + (size_t)row * C_ + col)       = make_float2(acc[mt][nt][0], acc[mt][nt][1]);
            *(float2*)(Cm + (size_t)(row + 8) * C_ + col) = make_float2(acc[mt][nt][2], acc[mt][nt][3]);
        }
    }
}

// ---------------------------------------------------------------------------
// HMMA fp16 flash attention (causal), SOFTWARE-PIPELINED:
// iter kt interleaves PV(kt) with QK(kt+1) (independent accumulator chains);
// softmax(kt+1) at iter end. Skewed K/V double buffers: iter kt loads
// K(kt+2)->Kstage kt%2 and V(kt+1)->Vstage (kt+1)%2. One barrier per iter.
// ---------------------------------------------------------------------------
#define FST    136
#define FKV    (64 * FST)
#define FQ     (128 * FST)

__global__ __launch_bounds__(256, 2) void flash_mma()
{
    extern __shared__ __half fsm[];
    __half* sQ = fsm;                       // [128][FST]
    __half* sK = sQ + FQ;                   // 2 stages [64][FST]
    __half* sV = sK + 2 * FKV;              // 2 stages [64][FST]

    const int tid = threadIdx.x, wid = tid >> 5, lane = tid & 31;
    const int qb = gridDim.x - 1 - blockIdx.x;
    const int h  = blockIdx.y;
    const int b  = blockIdx.z;

    const size_t qrow0 = (size_t)(b * T_ + qb * 128) * C_ + h * HD_;
    const size_t krow0 = (size_t)(b * T_) * C_ + h * HD_;

    auto load_k_slice = [&](int kt, int i) {
        __half* base = sK + (kt & 1) * FKV;
        int idx = tid + i * 256;
        int r = idx >> 4, c8 = (idx & 15) * 8;
        CP_ASYNC16(smem_u32(base + r * FST + c8),
                   g_kf + krow0 + (size_t)(kt * 64 + r) * C_ + c8);
    };
    auto load_v_slice = [&](int kt, int i) {
        __half* base = sV + (kt & 1) * FKV;
        int idx = tid + i * 256;
        int r = idx >> 4, c8 = (idx & 15) * 8;
        CP_ASYNC16(smem_u32(base + r * FST + c8),
                   g_vf + krow0 + (size_t)(kt * 64 + r) * C_ + c8);
    };

    const int nkt = 2 * qb + 2;

    for (int i = tid; i < 2048; i += 256) {
        int r = i >> 4, c8 = (i & 15) * 8;
        CP_ASYNC16(smem_u32(sQ + r * FST + c8), g_qf + qrow0 + (size_t)r * C_ + c8);
    }
    #pragma unroll
    for (int i = 0; i < 4; i++) load_k_slice(0, i);
    #pragma unroll
    for (int i = 0; i < 4; i++) load_v_slice(0, i);
    #pragma unroll
    for (int i = 0; i < 4; i++) load_k_slice(1, i);   // nkt >= 2 always
    CP_COMMIT();
    CP_WAIT0();
    __syncthreads();

    const int g  = lane >> 2;
    const int t4 = lane & 3;
    const int a_row = wid * 16 + (lane & 15);
    const int a_c8  = (lane >> 4) * 8;
    const int b_row = (lane & 7) + ((lane >> 4) << 3);
    const int b_c8  = ((lane >> 3) & 1) * 8;
    const int v_row = lane & 15;
    const int v_c8  = (lane >> 4) * 8;

    unsigned bones[2];
    bones[0] = bones[1] = (lane < 4) ? 0x3C003C00u : 0u;

    float lacc[4] = {0.f, 0.f, 0.f, 0.f};
    float oacc[16][4];
    #pragma unroll
    for (int dt = 0; dt < 16; dt++)
        #pragma unroll
        for (int r = 0; r < 4; r++) oacc[dt][r] = 0.f;

    unsigned ph[4][4];

    // --- prologue: QK(0) + softmax(0) -> ph ---
    {
        float sacc[8][4];
        #pragma unroll
        for (int nt = 0; nt < 8; nt++)
            #pragma unroll
            for (int r = 0; r < 4; r++) sacc[nt][r] = 0.f;
        #pragma unroll
        for (int k16 = 0; k16 < 8; k16++) {
            unsigned ah[4];
            ldmatrix_x4(ah, smem_u32(sQ + a_row * FST + k16 * 16 + a_c8));
            #pragma unroll
            for (int nt2 = 0; nt2 < 4; nt2++) {
                unsigned bh[4];
                ldmatrix_x4(bh, smem_u32(sK + (nt2 * 16 + b_row) * FST + k16 * 16 + b_c8));
                #pragma unroll
                for (int t = 0; t < 2; t++)
                    mma_f16(sacc[nt2 * 2 + t], ah, bh + 2 * t);
            }
        }
        if (0 >= 2 * qb) {   // qb == 0: tile 0 is diagonal
            const int row0 = qb * 128 + wid * 16 + g;
            #pragma unroll
            for (int nt = 0; nt < 8; nt++) {
                const int col = nt * 8 + 2 * t4;
                if (col     > row0)     sacc[nt][0] = -1e30f;
                if (col + 1 > row0)     sacc[nt][1] = -1e30f;
                if (col     > row0 + 8) sacc[nt][2] = -1e30f;
                if (col + 1 > row0 + 8) sacc[nt][3] = -1e30f;
            }
        }
        #pragma unroll
        for (int kt2 = 0; kt2 < 4; kt2++) {
            #pragma unroll
            for (int hf = 0; hf < 2; hf++) {
                const float* sp = sacc[2 * kt2 + hf];
                ph[kt2][hf * 2 + 0] = ex2_h2(pack_h2(sp[0] - FMAX_REF, sp[1] - FMAX_REF));
                ph[kt2][hf * 2 + 1] = ex2_h2(pack_h2(sp[2] - FMAX_REF, sp[3] - FMAX_REF));
            }
        }
    }

    // --- pipelined mainloop ---
    for (int kt = 0; kt < nkt; kt++) {
        if (kt > 0) { CP_WAIT0(); __syncthreads(); }

        __half* Va = sV + (kt & 1) * FKV;          // V(kt)
        __half* Kb = sK + ((kt + 1) & 1) * FKV;    // K(kt+1)
        const bool pf = (kt + 1 < nkt);
        const bool lk = (kt + 2 < nkt);

        float sacc[8][4];
        if (pf) {
            #pragma unroll
            for (int nt = 0; nt < 8; nt++)
                #pragma unroll
                for (int r = 0; r < 4; r++) sacc[nt][r] = 0.f;
        }

        #pragma unroll
        for (int j = 0; j < 8; j++) {
            const int kt2 = j >> 1, dq = j & 1;
            // chain #1: QK(kt+1) sub-block j
            if (pf) {
                unsigned ah[4];
                ldmatrix_x4(ah, smem_u32(sQ + a_row * FST + j * 16 + a_c8));
                #pragma unroll
                for (int nt2 = 0; nt2 < 4; nt2++) {
                    unsigned bh[4];
                    ldmatrix_x4(bh, smem_u32(Kb + (nt2 * 16 + b_row) * FST + j * 16 + b_c8));
                    #pragma unroll
                    for (int t = 0; t < 2; t++)
                        mma_f16(sacc[nt2 * 2 + t], ah, bh + 2 * t);
                }
            }
            // prefetch: K(kt+2) on j<4, V(kt+1) on j>=4
            if (j < 4) { if (lk) load_k_slice(kt + 2, j); }
            else       { if (pf) load_v_slice(kt + 1, j - 4); }
            // chain #2: PV(kt) sub-block (kt2, dq)
            #pragma unroll
            for (int dh = 0; dh < 2; dh++) {
                unsigned vh[2][4];
                #pragma unroll
                for (int d = 0; d < 2; d++) {
                    const int dt2 = dq * 4 + dh * 2 + d;
                    ldmatrix_x4_trans(vh[d],
                        smem_u32(Va + (kt2 * 16 + v_row) * FST + dt2 * 16 + v_c8));
                }
                #pragma unroll
                for (int d = 0; d < 2; d++)
                    #pragma unroll
                    for (int n = 0; n < 2; n++)
                        mma_f16(oacc[(dq * 4 + dh * 2 + d) * 2 + n], ph[kt2], vh[d] + 2 * n);
            }
        }
        // l += P(kt) * ones
        #pragma unroll
        for (int kt2 = 0; kt2 < 4; kt2++)
            mma_f16(lacc, ph[kt2], bones);

        if (pf) CP_COMMIT();

        // softmax(kt+1): mask + ex2 -> ph
        if (pf) {
            const int jt = kt + 1;
            if (jt >= 2 * qb) {
                const int row0 = qb * 128 + wid * 16 + g;
                #pragma unroll
                for (int nt = 0; nt < 8; nt++) {
                    const int col = jt * 64 + nt * 8 + 2 * t4;
                    if (col     > row0)     sacc[nt][0] = -1e30f;
                    if (col + 1 > row0)     sacc[nt][1] = -1e30f;
                    if (col     > row0 + 8) sacc[nt][2] = -1e30f;
                    if (col + 1 > row0 + 8) sacc[nt][3] = -1e30f;
                }
            }
            #pragma unroll
            for (int kt2 = 0; kt2 < 4; kt2++) {
                #pragma unroll
                for (int hf = 0; hf < 2; hf++) {
                    const float* sp = sacc[2 * kt2 + hf];
                    ph[kt2][hf * 2 + 0] = ex2_h2(pack_h2(sp[0] - FMAX_REF, sp[1] - FMAX_REF));
                    ph[kt2][hf * 2 + 1] = ex2_h2(pack_h2(sp[2] - FMAX_REF, sp[3] - FMAX_REF));
                }
            }
        }
    }

    // epilogue
    float l0 = __shfl_sync(0xffffffffu, lacc[0], lane & 28);
    float l1 = __shfl_sync(0xffffffffu, lacc[2], lane & 28);
    const float inv0 = 1.f / l0, inv1 = 1.f / l1;
    __half* yb = g_yf + (size_t)(b * T_ + qb * 128 + wid * 16) * C_ + h * HD_;
    #pragma unroll
    for (int dt = 0; dt < 16; dt++) {
        const int col = dt * 8 + 2 * t4;
        *(__half2*)(yb + (size_t)g * C_ + col) =
            __float22half2_rn(make_float2(oacc[dt][0] * inv0, oacc[dt][1] * inv0));
        *(__half2*)(yb + (size_t)(g + 8) * C_ + col) =
            __float22half2_rn(make_float2(oacc[dt][2] * inv1, oacc[dt][3] * inv1));
    }
}

// ---------------------------------------------------------------------------
// Launch
// ---------------------------------------------------------------------------
extern "C" void kernel_launch(void* const* d_in, const int* in_sizes, int n_in,
                              void* d_out, int out_size)
{
    (void)in_sizes; (void)n_in; (void)out_size;
    const float* x     = (const float*)d_in[0];
    const float* ve    = (const float*)d_in[1];
    const float* cosb  = (const float*)d_in[2];
    const float* sinb  = (const float*)d_in[3];
    const float* Wq    = (const float*)d_in[4];
    const float* Wk    = (const float*)d_in[5];
    const float* Wv    = (const float*)d_in[6];
    const float* Wgate = (const float*)d_in[7];
    const float* Wproj = (const float*)d_in[8];
    float* out = (float*)d_out;

    __half *xf, *yf;
    cudaGetSymbolAddress((void**)&xf, g_xf);
    cudaGetSymbolAddress((void**)&yf, g_yf);

    prep_inputs<<<dim3(64, 64, 5), dim3(32, 8)>>>(x, Wq, Wk, Wv, Wproj);

    const int gemm_smem = NSTAGE * STAGE_E * (int)sizeof(__half);
    cudaFuncSetAttribute(gemm_qkv_fused, cudaFuncAttributeMaxDynamicSharedMemorySize, gemm_smem);
    cudaFuncSetAttribute(gemm_proj,      cudaFuncAttributeMaxDynamicSharedMemorySize, gemm_smem);
    gemm_qkv_fused<<<dim3(C_/128, M_/128, 3), 256, gemm_smem>>>(xf, x, ve, cosb, sinb, Wgate);

    const int fsmem = (FQ + 4 * FKV) * (int)sizeof(__half);
    cudaFuncSetAttribute(flash_mma, cudaFuncAttributeMaxDynamicSharedMemorySize, fsmem);
    flash_mma<<<dim3(T_/128, NH_, B_), 256, fsmem>>>();

    gemm_proj<<<dim3(C_/128, M_/128), 256, gemm_smem>>>(yf, out);
}

// round 16
// speedup vs baseline: 1.2284x; 1.2284x over previous
#include <cuda_runtime.h>
#include <cuda_fp16.h>
#include <math.h>

// Problem constants
#define B_       2
#define T_       2048
#define C_       2048
#define NH_      16
#define HD_      128
#define GATE_CH_ 32
#define M_       (B_*T_)   // 4096 rows

// ---------------------------------------------------------------------------
// Scratch (device globals: allocation-free per harness rules)
// ---------------------------------------------------------------------------
__device__ __half g_xf[(size_t)M_*C_];
__device__ __half g_yf[(size_t)M_*C_];
__device__ __half g_qf[(size_t)M_*C_];
__device__ __half g_kf[(size_t)M_*C_];
__device__ __half g_vf[(size_t)M_*C_];
__device__ __half g_wt[4][(size_t)C_*C_];   // transposed [N][K] Wq,Wk,Wv,Wproj

// ---------------------------------------------------------------------------
// PTX helpers
// ---------------------------------------------------------------------------
__device__ __forceinline__ unsigned smem_u32(const void* p) {
    unsigned a;
    asm("{ .reg .u64 t; cvta.to.shared.u64 t, %1; cvt.u32.u64 %0, t; }"
        : "=r"(a) : "l"(p));
    return a;
}

#define CP_ASYNC16(dst_u32, src_ptr) \
    asm volatile("cp.async.cg.shared.global [%0], [%1], 16;" \
                 :: "r"(dst_u32), "l"(src_ptr))
#define CP_COMMIT() asm volatile("cp.async.commit_group;" ::: "memory")
#define CP_WAIT0()  asm volatile("cp.async.wait_group 0;" ::: "memory")
#define CP_WAIT1()  asm volatile("cp.async.wait_group 1;" ::: "memory")

__device__ __forceinline__ void ldmatrix_x4(unsigned* r, unsigned addr) {
    asm volatile("ldmatrix.sync.aligned.m8n8.x4.shared.b16 {%0,%1,%2,%3}, [%4];"
                 : "=r"(r[0]), "=r"(r[1]), "=r"(r[2]), "=r"(r[3]) : "r"(addr));
}
__device__ __forceinline__ void ldmatrix_x4_trans(unsigned* r, unsigned addr) {
    asm volatile("ldmatrix.sync.aligned.m8n8.x4.trans.shared.b16 {%0,%1,%2,%3}, [%4];"
                 : "=r"(r[0]), "=r"(r[1]), "=r"(r[2]), "=r"(r[3]) : "r"(addr));
}
__device__ __forceinline__ void mma_f16(float* c, const unsigned* a, const unsigned* b) {
    asm volatile(
        "mma.sync.aligned.m16n8k16.row.col.f32.f16.f16.f32 "
        "{%0,%1,%2,%3}, {%4,%5,%6,%7}, {%8,%9}, {%0,%1,%2,%3};"
        : "+f"(c[0]), "+f"(c[1]), "+f"(c[2]), "+f"(c[3])
        : "r"(a[0]), "r"(a[1]), "r"(a[2]), "r"(a[3]), "r"(b[0]), "r"(b[1]));
}
__device__ __forceinline__ unsigned pack_h2(float lo, float hi) {
    __half2 h = __float22half2_rn(make_float2(lo, hi));
    return *reinterpret_cast<unsigned*>(&h);
}
// two fp16 exp2's in one MUFU op
__device__ __forceinline__ unsigned ex2_h2(unsigned x) {
    unsigned y;
    asm("ex2.approx.f16x2 %0, %1;" : "=r"(y) : "r"(x));
    return y;
}
__device__ __forceinline__ float warp_sum(float v) {
    #pragma unroll
    for (int d = 16; d >= 1; d >>= 1) v += __shfl_xor_sync(0xffffffffu, v, d);
    return v;
}

// scale * log2(e), folded into q at QKV epilogue
#define QSC (0.08838834764831845f * 1.4426950408889634f)
// fixed softmax reference (log2 units). |t| <= 16.33 by Cauchy-Schwarz on
// RMS-normed q,k, so p = 2^(t-5) in [2^-21.3, 2^11.3]: provably no fp16
// overflow and no subnormal flush-to-zero of any term.
#define FMAX_REF 5.0f

// ---------------------------------------------------------------------------
// prep_inputs: z<4: transpose W[K][N] fp32 -> g_wt[z][N][K] fp16;
//              z=4: convert x fp32 -> g_xf fp16.
// grid (64, 64, 5), block (32, 8).
// ---------------------------------------------------------------------------
__global__ __launch_bounds__(256) void prep_inputs(
    const float* __restrict__ x,
    const float* __restrict__ Wq, const float* __restrict__ Wk,
    const float* __restrict__ Wv, const float* __restrict__ Wproj)
{
    __shared__ float tile[32][33];
    const int z = blockIdx.z;
    const int tid = threadIdx.y * 32 + threadIdx.x;

    if (z == 4) {
        const int idx0 = (blockIdx.y * 64 + blockIdx.x) * 256 + tid;
        #pragma unroll
        for (int r = 0; r < 2; r++) {
            const int i = idx0 + r * (64 * 64 * 256);
            float4 v = ((const float4*)x)[i];
            __half2* op = (__half2*)(g_xf + (size_t)i * 4);
            op[0] = __float22half2_rn(make_float2(v.x, v.y));
            op[1] = __float22half2_rn(make_float2(v.z, v.w));
        }
        return;
    }

    const float* W = (z == 0) ? Wq : (z == 1) ? Wk : (z == 2) ? Wv : Wproj;
    __half* out = g_wt[z];
    int k0 = blockIdx.y * 32, n0 = blockIdx.x * 32;
    int tx = threadIdx.x, ty = threadIdx.y;
    #pragma unroll
    for (int r = 0; r < 4; r++)
        tile[ty + 8 * r][tx] = W[(size_t)(k0 + ty + 8 * r) * C_ + n0 + tx];
    __syncthreads();
    #pragma unroll
    for (int r = 0; r < 4; r++) {
        float v = tile[tx][ty + 8 * r];
        out[(size_t)(n0 + ty + 8 * r) * C_ + k0 + tx] = __float2half(v);
    }
}

// ---------------------------------------------------------------------------
// HMMA fp16 GEMM mainloop. 128x128 CTA tile, 8 warps (4x2), k-chunk 64,
// cp.async 3-stage pipeline, loads spread across the k16 blocks,
// one barrier per chunk.
// ---------------------------------------------------------------------------
#define KC        64
#define AS_STRIDE 72                        // fp16 elems per smem row (144B)
#define TILE_E    (128 * AS_STRIDE)         // 9216 elems
#define STAGE_E   (2 * TILE_E)              // A | B
#define NSTAGE    3

__device__ __forceinline__ void gemm_mainloop(
    const __half* __restrict__ A, const __half* __restrict__ Bm,
    int m0, int n0, int K, __half* smb, float acc[2][8][4])
{
    const int tid = threadIdx.x, wid = tid >> 5, lane = tid & 31;
    const int NCH = K / KC;
    const int wm = wid & 3;
    const int wn = wid >> 2;

    auto load_slice = [&](int c, int s, int i) {
        const int k0 = c * KC;
        __half* base = smb + s * STAGE_E;
        int cidx = tid + i * 256;          // 0..1023
        int row  = cidx >> 3;
        int col8 = (cidx & 7) * 8;
        unsigned so = smem_u32(base + row * AS_STRIDE + col8);
        CP_ASYNC16(so,              A  + (size_t)(m0 + row) * K + k0 + col8);
        CP_ASYNC16(so + TILE_E * 2, Bm + (size_t)(n0 + row) * K + k0 + col8);
    };

    #pragma unroll
    for (int mt = 0; mt < 2; mt++)
        #pragma unroll
        for (int nt = 0; nt < 8; nt++)
            #pragma unroll
            for (int r = 0; r < 4; r++) acc[mt][nt][r] = 0.f;

    #pragma unroll
    for (int i = 0; i < 4; i++) load_slice(0, 0, i);
    CP_COMMIT();
    #pragma unroll
    for (int i = 0; i < 4; i++) load_slice(1, 1, i);
    CP_COMMIT();

    const int a_row = wm * 32 + (lane & 15);
    const int a_k8  = (lane >> 4) * 8;
    const int b_r   = lane & 7;
    const int b_grp = lane >> 3;
    const int b_row = wn * 64 + (b_grp >> 1) * 8 + b_r;
    const int b_k8  = (b_grp & 1) * 8;

    for (int c = 0; c < NCH; c++) {
        if (c + 1 < NCH) CP_WAIT1();
        else             CP_WAIT0();
        __syncthreads();

        const __half* st = smb + (c % NSTAGE) * STAGE_E;
        const __half* sA = st;
        const __half* sB = st + TILE_E;
        const bool pf = (c + 2 < NCH);
        const int  ps = (c + 2) % NSTAGE;

        #pragma unroll
        for (int k16 = 0; k16 < 4; k16++) {
            if (pf) load_slice(c + 2, ps, k16);
            const int kb = k16 * 16;
            unsigned ah[2][4];
            #pragma unroll
            for (int mt = 0; mt < 2; mt++)
                ldmatrix_x4(ah[mt], smem_u32(sA + (a_row + mt * 16) * AS_STRIDE + kb + a_k8));
            unsigned bh[4][4];
            #pragma unroll
            for (int j = 0; j < 4; j++)
                ldmatrix_x4(bh[j], smem_u32(sB + (b_row + j * 16) * AS_STRIDE + kb + b_k8));
            #pragma unroll
            for (int j = 0; j < 4; j++)
                #pragma unroll
                for (int t = 0; t < 2; t++)
                    #pragma unroll
                    for (int mt = 0; mt < 2; mt++)
                        mma_f16(acc[mt][j * 2 + t], ah[mt], bh[j] + t * 2);
        }
        if (pf) CP_COMMIT();
    }
    __syncthreads();   // protect epilogue smem reuse
}

// ---------------------------------------------------------------------------
// Fused QKV GEMM + prep epilogue. z=0: q (rope+rms, pre-scaled by QSC);
// z=1: k (rope+rms); z=2: v + gate*ve. 128 cols per tile = one full head.
// ---------------------------------------------------------------------------
#define EST 130   // fp32 epilogue smem row stride

__global__ __launch_bounds__(256, 2) void gemm_qkv_fused(
    const __half* __restrict__ A,
    const float* __restrict__ x, const float* __restrict__ ve,
    const float* __restrict__ cosb, const float* __restrict__ sinb,
    const float* __restrict__ Wgate)
{
    extern __shared__ __half smb[];
    const int z = blockIdx.z;
    const int m0 = blockIdx.y * 128, n0 = blockIdx.x * 128;

    float acc[2][8][4];
    gemm_mainloop(A, g_wt[z], m0, n0, C_, smb, acc);

    // spill fp32 tile to smem (stage buffers are free now)
    const int tid = threadIdx.x, wid = tid >> 5, lane = tid & 31;
    const int wm = wid & 3, wn = wid >> 2;
    const int cg = lane >> 2, ct = lane & 3;
    float* ft = (float*)smb;
    #pragma unroll
    for (int mt = 0; mt < 2; mt++) {
        const int r = wm * 32 + mt * 16 + cg;
        #pragma unroll
        for (int nt = 0; nt < 8; nt++) {
            const int cc = wn * 64 + nt * 8 + ct * 2;
            ft[r * EST + cc]           = acc[mt][nt][0];
            ft[r * EST + cc + 1]       = acc[mt][nt][1];
            ft[(r + 8) * EST + cc]     = acc[mt][nt][2];
            ft[(r + 8) * EST + cc + 1] = acc[mt][nt][3];
        }
    }
    __syncthreads();

    const int h = n0 >> 7;   // head index
    if (z < 2) {
        __half* gout = (z == 0) ? g_qf : g_kf;
        const float post = (z == 0) ? QSC : 1.f;
        for (int rr = 0; rr < 16; rr++) {
            const int r = wid * 16 + rr;
            const int row = m0 + r;
            const int t = row & (T_ - 1);
            const float* fr = ft + r * EST;
            const float* cr = cosb + (size_t)t * 64;
            const float* sr = sinb + (size_t)t * 64;
            const int d0 = lane, d1 = lane + 32;
            float x1a = fr[d0], x2a = fr[d0 + 64];
            float x1b = fr[d1], x2b = fr[d1 + 64];
            float ca = cr[d0], sa = sr[d0], cb = cr[d1], sb = sr[d1];
            float o1a =  x1a * ca + x2a * sa;
            float o2a = -x1a * sa + x2a * ca;
            float o1b =  x1b * cb + x2b * sb;
            float o2b = -x1b * sb + x2b * cb;
            float ss = warp_sum(o1a*o1a + o2a*o2a + o1b*o1b + o2b*o2b);
            float rn = rsqrtf(ss * (1.f / 128.f) + 1e-6f) * post;
            __half* dst = gout + (size_t)row * C_ + n0;
            dst[d0]      = __float2half(o1a * rn);
            dst[d0 + 64] = __float2half(o2a * rn);
            dst[d1]      = __float2half(o1b * rn);
            dst[d1 + 64] = __float2half(o2b * rn);
        }
    } else {
        for (int rr = 0; rr < 16; rr++) {
            const int r = wid * 16 + rr;
            const int row = m0 + r;
            const float* fr = ft + r * EST;
            float sg = warp_sum(x[(size_t)row * C_ + lane] * Wgate[lane * NH_ + h]);
            float gt = 2.f / (1.f + __expf(-sg));
            __half* dst = g_vf + (size_t)row * C_ + n0;
            const float* vep = ve + (size_t)row * C_ + n0;
            #pragma unroll
            for (int i2 = 0; i2 < 4; i2++) {
                const int d = lane + i2 * 32;
                dst[d] = __float2half(fr[d] + gt * vep[d]);
            }
        }
    }
}

// proj GEMM: plain fp32 epilogue to out
__global__ __launch_bounds__(256, 2) void gemm_proj(
    const __half* __restrict__ A, float* __restrict__ Cm)
{
    extern __shared__ __half smb[];
    const int m0 = blockIdx.y * 128, n0 = blockIdx.x * 128;
    float acc[2][8][4];
    gemm_mainloop(A, g_wt[3], m0, n0, C_, smb, acc);

    const int tid = threadIdx.x, wid = tid >> 5, lane = tid & 31;
    const int wm = wid & 3, wn = wid >> 2;
    const int cg = lane >> 2, ct = lane & 3;
    #pragma unroll
    for (int mt = 0; mt < 2; mt++) {
        const int row = m0 + wm * 32 + mt * 16 + cg;
        #pragma unroll
        for (int nt = 0; nt < 8; nt++) {
            const int col = n0 + wn * 64 + nt * 8 + ct * 2;
            *(float2*)(Cm + (size_t)row * C_ + col)       = make_float2(acc[mt][nt][0], acc[mt][nt][1]);
            *(float2*)(Cm + (size_t)(row + 8) * C_ + col) = make_float2(acc[mt][nt][2], acc[mt][nt][3]);
        }
    }
}

// ---------------------------------------------------------------------------
// HMMA fp16 flash attention (causal). BM=128, BN=64, HD=128.
// Fixed-reference softmax; P computed with ex2.approx.f16x2 (half MUFU ops,
// output pre-packed for MMA). l via ones-column MMA. KV loads for kt+1 spread
// across the QK k16 loop; one barrier per kt.
// ---------------------------------------------------------------------------
#define FST    136                 // smem row stride (fp16 elems), 272B
#define FKV    (64 * FST)
#define FQ     (128 * FST)

__global__ __launch_bounds__(256, 2) void flash_mma()
{
    extern __shared__ __half fsm[];
    __half* sQ  = fsm;                      // [128][FST]
    __half* sKV = sQ + FQ;                  // 2 stages x (K|V)[64][FST]

    const int tid = threadIdx.x, wid = tid >> 5, lane = tid & 31;
    const int qb = gridDim.x - 1 - blockIdx.x;   // big tiles first
    const int h  = blockIdx.y;
    const int b  = blockIdx.z;

    const size_t qrow0 = (size_t)(b * T_ + qb * 128) * C_ + h * HD_;
    const size_t krow0 = (size_t)(b * T_) * C_ + h * HD_;

    auto load_kv_slice = [&](int kt, int s, int i) {
        __half* base = sKV + s * (2 * FKV);
        const size_t kb0 = krow0 + (size_t)(kt * 64) * C_;
        int idx = tid + i * 256;
        int r = idx >> 4, c8 = (idx & 15) * 8;
        size_t go = kb0 + (size_t)r * C_ + c8;
        unsigned off = r * FST + c8;
        CP_ASYNC16(smem_u32(base + off),       g_kf + go);
        CP_ASYNC16(smem_u32(base + FKV + off), g_vf + go);
    };

    for (int i = tid; i < 2048; i += 256) {
        int r = i >> 4, c8 = (i & 15) * 8;
        CP_ASYNC16(smem_u32(sQ + r * FST + c8), g_qf + qrow0 + (size_t)r * C_ + c8);
    }
    #pragma unroll
    for (int i = 0; i < 4; i++) load_kv_slice(0, 0, i);
    CP_COMMIT();
    CP_WAIT0();
    __syncthreads();

    const int g  = lane >> 2;
    const int t4 = lane & 3;
    const int a_row = wid * 16 + (lane & 15);
    const int a_c8  = (lane >> 4) * 8;
    const int b_row = (lane & 7) + ((lane >> 4) << 3);
    const int b_c8  = ((lane >> 3) & 1) * 8;
    const int v_row = lane & 15;
    const int v_c8  = (lane >> 4) * 8;

    // ones B-fragment: column n=0 of an m16n8k16 B tile is all 1.0 (fp16).
    unsigned bones[2];
    bones[0] = bones[1] = (lane < 4) ? 0x3C003C00u : 0u;

    float lacc[4] = {0.f, 0.f, 0.f, 0.f};
    float oacc[16][4];
    #pragma unroll
    for (int dt = 0; dt < 16; dt++)
        #pragma unroll
        for (int r = 0; r < 4; r++) oacc[dt][r] = 0.f;

    const int nkt = 2 * qb + 2;

    for (int kt = 0; kt < nkt; kt++) {
        const int s = kt & 1;
        if (kt > 0) { CP_WAIT0(); __syncthreads(); }

        __half* Kh = sKV + s * (2 * FKV);
        __half* Vh = Kh + FKV;
        const bool pf = (kt + 1 < nkt);

        // --- S = Q K^T (Q pre-scaled by QSC), KV(kt+1) loads interleaved ---
        float sacc[8][4];
        #pragma unroll
        for (int nt = 0; nt < 8; nt++)
            #pragma unroll
            for (int r = 0; r < 4; r++) sacc[nt][r] = 0.f;

        #pragma unroll
        for (int k16 = 0; k16 < 8; k16++) {
            if (pf && !(k16 & 1)) load_kv_slice(kt + 1, s ^ 1, k16 >> 1);
            unsigned ah[4];
            ldmatrix_x4(ah, smem_u32(sQ + a_row * FST + k16 * 16 + a_c8));
            #pragma unroll
            for (int nt2 = 0; nt2 < 4; nt2++) {
                unsigned bh[4];
                ldmatrix_x4(bh, smem_u32(Kh + (nt2 * 16 + b_row) * FST + k16 * 16 + b_c8));
                #pragma unroll
                for (int t = 0; t < 2; t++)
                    mma_f16(sacc[nt2 * 2 + t], ah, bh + 2 * t);
            }
        }
        if (pf) CP_COMMIT();

        if (kt >= 2 * qb) {
            const int row0 = qb * 128 + wid * 16 + g;
            #pragma unroll
            for (int nt = 0; nt < 8; nt++) {
                const int col = kt * 64 + nt * 8 + 2 * t4;
                if (col     > row0)     sacc[nt][0] = -1e30f;
                if (col + 1 > row0)     sacc[nt][1] = -1e30f;
                if (col     > row0 + 8) sacc[nt][2] = -1e30f;
                if (col + 1 > row0 + 8) sacc[nt][3] = -1e30f;
            }
        }

        // --- P = 2^(t - FMAX_REF) via f16x2 MUFU; result is MMA-ready ---
        unsigned ph[4][4];
        #pragma unroll
        for (int kt2 = 0; kt2 < 4; kt2++) {
            #pragma unroll
            for (int half = 0; half < 2; half++) {
                const float* sp = sacc[2 * kt2 + half];
                ph[kt2][half * 2 + 0] =
                    ex2_h2(pack_h2(sp[0] - FMAX_REF, sp[1] - FMAX_REF));
                ph[kt2][half * 2 + 1] =
                    ex2_h2(pack_h2(sp[2] - FMAX_REF, sp[3] - FMAX_REF));
            }
        }
        #pragma unroll
        for (int kt2 = 0; kt2 < 4; kt2++)
            mma_f16(lacc, ph[kt2], bones);

        #pragma unroll
        for (int kt2 = 0; kt2 < 4; kt2++) {
            #pragma unroll
            for (int dp = 0; dp < 4; dp++) {
                unsigned vh[2][4];
                #pragma unroll
                for (int d = 0; d < 2; d++) {
                    const int dt2 = dp * 2 + d;
                    ldmatrix_x4_trans(vh[d], smem_u32(Vh + (kt2 * 16 + v_row) * FST + dt2 * 16 + v_c8));
                }
                #pragma unroll
                for (int d = 0; d < 2; d++)
                    #pragma unroll
                    for (int n = 0; n < 2; n++)
                        mma_f16(oacc[(dp * 2 + d) * 2 + n], ph[kt2], vh[d] + 2 * n);
            }
        }
    }

    // epilogue: broadcast l from ct==0 lanes, normalize, store fp16
    float l0 = __shfl_sync(0xffffffffu, lacc[0], lane & 28);
    float l1 = __shfl_sync(0xffffffffu, lacc[2], lane & 28);
    const float inv0 = 1.f / l0, inv1 = 1.f / l1;
    __half* yb = g_yf + (size_t)(b * T_ + qb * 128 + wid * 16) * C_ + h * HD_;
    #pragma unroll
    for (int dt = 0; dt < 16; dt++) {
        const int col = dt * 8 + 2 * t4;
        *(__half2*)(yb + (size_t)g * C_ + col) =
            __float22half2_rn(make_float2(oacc[dt][0] * inv0, oacc[dt][1] * inv0));
        *(__half2*)(yb + (size_t)(g + 8) * C_ + col) =
            __float22half2_rn(make_float2(oacc[dt][2] * inv1, oacc[dt][3] * inv1));
    }
}

// ---------------------------------------------------------------------------
// Launch
// ---------------------------------------------------------------------------
extern "C" void kernel_launch(void* const* d_in, const int* in_sizes, int n_in,
                              void* d_out, int out_size)
{
    (void)in_sizes; (void)n_in; (void)out_size;
    const float* x     = (const float*)d_in[0];
    const float* ve    = (const float*)d_in[1];
    const float* cosb  = (const float*)d_in[2];
    const float* sinb  = (const float*)d_in[3];
    const float* Wq    = (const float*)d_in[4];
    const float* Wk    = (const float*)d_in[5];
    const float* Wv    = (const float*)d_in[6];
    const float* Wgate = (const float*)d_in[7];
    const float* Wproj = (const float*)d_in[8];
    float* out = (float*)d_out;

    __half *xf, *yf;
    cudaGetSymbolAddress((void**)&xf, g_xf);
    cudaGetSymbolAddress((void**)&yf, g_yf);

    prep_inputs<<<dim3(64, 64, 5), dim3(32, 8)>>>(x, Wq, Wk, Wv, Wproj);

    const int gemm_smem = NSTAGE * STAGE_E * (int)sizeof(__half);  // 110592 B
    cudaFuncSetAttribute(gemm_qkv_fused, cudaFuncAttributeMaxDynamicSharedMemorySize, gemm_smem);
    cudaFuncSetAttribute(gemm_proj,      cudaFuncAttributeMaxDynamicSharedMemorySize, gemm_smem);
    gemm_qkv_fused<<<dim3(C_/128, M_/128, 3), 256, gemm_smem>>>(xf, x, ve, cosb, sinb, Wgate);

    const int fsmem = (FQ + 4 * FKV) * (int)sizeof(__half);  // 104448 B
    cudaFuncSetAttribute(flash_mma, cudaFuncAttributeMaxDynamicSharedMemorySize, fsmem);
    flash_mma<<<dim3(T_/128, NH_, B_), 256, fsmem>>>();

    gemm_proj<<<dim3(C_/128, M_/128), 256, gemm_smem>>>(yf, out);
}